// round 3
// baseline (speedup 1.0000x reference)
#include <cuda_runtime.h>
#include <math.h>

#define Q 512
#define L 4096

// ---------------- scratch (no allocation allowed) ----------------
__device__ float g_p[L * 256];     // relu(protein @ Wc.T + bc)
__device__ float g_k[L * 64];      // relu(p @ W1.T + b1)
__device__ float g_pa[L * 64];     // k @ Wpa.T + bpa
__device__ float g_r[Q * 64];      // relu(reactions @ W2.T + b2)
__device__ float g_ra[Q * 64];     // r @ Wra.T + bra
__device__ float g_S[Q * 64];      // sum_l relu(ra+pa)
__device__ float g_T[L * 64];      // sum_q relu(ra+pa)
__device__ float g_rx[Q * 64];     // rxnfp
__device__ float g_prot[64];       // max_l (k + k*p_gate)

__global__ __launch_bounds__(256) void zero_kernel(float* s, float* prot, int n) {
    int i = blockIdx.x * blockDim.x + threadIdx.x;
    if (i < n) s[i] = 0.0f;
    if (i < 64) prot[i] = 0.0f;
}

// ---------------- generic tiled GEMM: C[m][n] = act(bias[n] + sum_k A[m][k]*W[n][k])
// BM=BN=64, BK=32, 256 threads, 4x4 per thread. M%64==0, N%64==0, K%32==0.
template <int ACT>  // 0 = none, 1 = relu
__global__ __launch_bounds__(256) void gemm_bias_act(
        const float* __restrict__ A, const float* __restrict__ W,
        const float* __restrict__ bias, float* __restrict__ C,
        int M, int N, int K) {
    __shared__ float As[32][68];
    __shared__ float Ws[32][68];
    const int bm = blockIdx.x * 64;
    const int bn = blockIdx.y * 64;
    const int tid = threadIdx.x;
    const int tx = tid & 15;   // n group
    const int ty = tid >> 4;   // m group
    float acc[4][4];
#pragma unroll
    for (int i = 0; i < 4; i++)
#pragma unroll
        for (int j = 0; j < 4; j++) acc[i][j] = 0.0f;

    for (int kk = 0; kk < K; kk += 32) {
#pragma unroll
        for (int i = 0; i < 8; i++) {
            int e = tid + i * 256;
            int k_ = e & 31, m_ = e >> 5;
            As[k_][m_] = A[(size_t)(bm + m_) * K + kk + k_];
        }
#pragma unroll
        for (int i = 0; i < 8; i++) {
            int e = tid + i * 256;
            int k_ = e & 31, n_ = e >> 5;
            Ws[k_][n_] = W[(size_t)(bn + n_) * K + kk + k_];
        }
        __syncthreads();
#pragma unroll
        for (int k = 0; k < 32; k++) {
            float4 av = *(const float4*)&As[k][ty * 4];
            float4 wv = *(const float4*)&Ws[k][tx * 4];
            float a[4] = {av.x, av.y, av.z, av.w};
            float w[4] = {wv.x, wv.y, wv.z, wv.w};
#pragma unroll
            for (int i = 0; i < 4; i++)
#pragma unroll
                for (int j = 0; j < 4; j++) acc[i][j] = fmaf(a[i], w[j], acc[i][j]);
        }
        __syncthreads();
    }
#pragma unroll
    for (int i = 0; i < 4; i++) {
        int m = bm + ty * 4 + i;
#pragma unroll
        for (int j = 0; j < 4; j++) {
            int n = bn + tx * 4 + j;
            float v = acc[i][j] + bias[n];
            if (ACT == 1) v = fmaxf(v, 0.0f);
            C[(size_t)m * N + n] = v;
        }
    }
}

// ---------------- outer-sum passes ----------------
// S[q][c] = sum_l relu(ra[q][c] + pa[l][c]).  block=(64,8): 16 q per block, 512 l per block.
__global__ __launch_bounds__(512) void outer_S_kernel(
        const float* __restrict__ ra, const float* __restrict__ pa,
        float* __restrict__ S) {
    __shared__ float spa[64][64];
    const int tx = threadIdx.x, ty = threadIdx.y;
    const int tid = ty * 64 + tx;
    const int q0 = blockIdx.x * 16 + ty * 2;
    const int l0 = blockIdx.y * 512;
    const float r0 = ra[q0 * 64 + tx];
    const float r1 = ra[(q0 + 1) * 64 + tx];
    float a0 = 0.0f, a1 = 0.0f;
    for (int lc = 0; lc < 512; lc += 64) {
        __syncthreads();
#pragma unroll
        for (int i = 0; i < 8; i++) {
            int e = tid + i * 512;
            spa[e >> 6][e & 63] = pa[(l0 + lc + (e >> 6)) * 64 + (e & 63)];
        }
        __syncthreads();
#pragma unroll
        for (int i = 0; i < 64; i++) {
            float v = spa[i][tx];
            a0 += fmaxf(r0 + v, 0.0f);
            a1 += fmaxf(r1 + v, 0.0f);
        }
    }
    atomicAdd(&S[q0 * 64 + tx], a0);
    atomicAdd(&S[(q0 + 1) * 64 + tx], a1);
}

// T[l][c] = sum_q relu(ra[q][c] + pa[l][c]). block=(64,8): 16 l per block, full Q loop.
__global__ __launch_bounds__(512) void outer_T_kernel(
        const float* __restrict__ ra, const float* __restrict__ pa,
        float* __restrict__ T) {
    __shared__ float sra[64][64];
    const int tx = threadIdx.x, ty = threadIdx.y;
    const int tid = ty * 64 + tx;
    const int l0 = blockIdx.x * 16 + ty * 2;
    const float p0 = pa[l0 * 64 + tx];
    const float p1 = pa[(l0 + 1) * 64 + tx];
    float a0 = 0.0f, a1 = 0.0f;
    for (int qc = 0; qc < Q; qc += 64) {
        __syncthreads();
#pragma unroll
        for (int i = 0; i < 8; i++) {
            int e = tid + i * 512;
            sra[e >> 6][e & 63] = ra[(qc + (e >> 6)) * 64 + (e & 63)];
        }
        __syncthreads();
#pragma unroll
        for (int i = 0; i < 64; i++) {
            float v = sra[i][tx];
            a0 += fmaxf(p0 + v, 0.0f);
            a1 += fmaxf(p1 + v, 0.0f);
        }
    }
    T[l0 * 64 + tx] = a0;
    T[(l0 + 1) * 64 + tx] = a1;
}

// ---------------- gates ----------------
// r_gate = sigmoid((S/L) @ Wa.T + ba); rx = r*(1+gate).  block=(64,8) over 8 q's.
__global__ __launch_bounds__(512) void gate_r_kernel(
        const float* __restrict__ S, const float* __restrict__ Wa,
        const float* __restrict__ ba, const float* __restrict__ r,
        float* __restrict__ rx) {
    __shared__ float sWa[64][65];
    __shared__ float sS[8][64];
    const int tx = threadIdx.x, ty = threadIdx.y;
    const int tid = ty * 64 + tx;
    const int q0 = blockIdx.x * 8;
#pragma unroll
    for (int i = 0; i < 8; i++) {
        int e = tid + i * 512;
        sWa[e >> 6][e & 63] = Wa[e];
    }
    sS[tid >> 6][tid & 63] = S[(q0 + (tid >> 6)) * 64 + (tid & 63)];
    __syncthreads();
    float acc = 0.0f;
#pragma unroll
    for (int j = 0; j < 64; j++) acc += sS[ty][j] * sWa[tx][j];
    float x = ba[tx] + acc * (1.0f / (float)L);
    float g = 1.0f / (1.0f + expf(-x));
    int idx = (q0 + ty) * 64 + tx;
    rx[idx] = r[idx] * (1.0f + g);
}

// p_gate = sigmoid((T/Q) @ Wa.T + ba); prot[c] = max_l k*(1+gate) via atomicMax (nonneg).
__global__ __launch_bounds__(512) void gate_p_kernel(
        const float* __restrict__ T, const float* __restrict__ Wa,
        const float* __restrict__ ba, const float* __restrict__ k,
        float* __restrict__ prot) {
    __shared__ float sWa[64][65];
    __shared__ float sT[8][64];
    __shared__ float skp[8][64];
    const int tx = threadIdx.x, ty = threadIdx.y;
    const int tid = ty * 64 + tx;
    const int l0 = blockIdx.x * 8;
#pragma unroll
    for (int i = 0; i < 8; i++) {
        int e = tid + i * 512;
        sWa[e >> 6][e & 63] = Wa[e];
    }
    sT[tid >> 6][tid & 63] = T[(l0 + (tid >> 6)) * 64 + (tid & 63)];
    __syncthreads();
    float acc = 0.0f;
#pragma unroll
    for (int j = 0; j < 64; j++) acc += sT[ty][j] * sWa[tx][j];
    float x = ba[tx] + acc * (1.0f / (float)Q);
    float g = 1.0f / (1.0f + expf(-x));
    float kv = k[(l0 + ty) * 64 + tx];
    skp[ty][tx] = kv * (1.0f + g);
    __syncthreads();
    if (ty == 0) {
        float m = skp[0][tx];
#pragma unroll
        for (int i = 1; i < 8; i++) m = fmaxf(m, skp[i][tx]);
        atomicMax((int*)&prot[tx], __float_as_int(m));  // all values >= 0
    }
}

// ---------------- MLP head: 8 q per block, 256 threads ----------------
__global__ __launch_bounds__(256) void head_kernel(
        const float* __restrict__ rx, const float* __restrict__ prot,
        const float* __restrict__ Wf1, const float* __restrict__ bf1,
        const float* __restrict__ Wf2, const float* __restrict__ bf2,
        const float* __restrict__ Wf3, const float* __restrict__ bf3,
        float* __restrict__ out) {
    __shared__ float sctx[8][128];
    __shared__ float sh1[8][256];
    __shared__ float sh2[8][128];
    const int tid = threadIdx.x;  // 256
    const int q0 = blockIdx.x * 8;
#pragma unroll
    for (int i = 0; i < 4; i++) {
        int e = tid + i * 256;
        int qq = e >> 7, cc = e & 127;
        sctx[qq][cc] = (cc < 64) ? rx[(q0 + qq) * 64 + cc] : prot[cc - 64];
    }
    __syncthreads();
    {
        float acc[8];
        float b = bf1[tid];
#pragma unroll
        for (int qq = 0; qq < 8; qq++) acc[qq] = b;
        for (int kk = 0; kk < 128; kk++) {
            float w = Wf1[tid * 128 + kk];
#pragma unroll
            for (int qq = 0; qq < 8; qq++) acc[qq] = fmaf(w, sctx[qq][kk], acc[qq]);
        }
#pragma unroll
        for (int qq = 0; qq < 8; qq++) {
            float v = acc[qq];
            sh1[qq][tid] = (v > 0.0f) ? v : 0.01f * v;
        }
    }
    __syncthreads();
    if (tid < 128) {
        float acc[8];
        float b = bf2[tid];
#pragma unroll
        for (int qq = 0; qq < 8; qq++) acc[qq] = b;
        for (int kk = 0; kk < 256; kk++) {
            float w = Wf2[tid * 256 + kk];
#pragma unroll
            for (int qq = 0; qq < 8; qq++) acc[qq] = fmaf(w, sh1[qq][kk], acc[qq]);
        }
#pragma unroll
        for (int qq = 0; qq < 8; qq++) {
            float v = acc[qq];
            sh2[qq][tid] = (v > 0.0f) ? v : 0.01f * v;
        }
    }
    __syncthreads();
    const int wq = tid >> 5, lane = tid & 31;
    float s = 0.0f;
#pragma unroll
    for (int kk = lane; kk < 128; kk += 32) s = fmaf(Wf3[kk], sh2[wq][kk], s);
#pragma unroll
    for (int off = 16; off; off >>= 1) s += __shfl_xor_sync(0xffffffffu, s, off);
    if (lane == 0) out[q0 + wq] = s + bf3[0];
}

// ---------------- launch ----------------
extern "C" void kernel_launch(void* const* d_in, const int* in_sizes, int n_in,
                              void* d_out, int out_size) {
    const float* reactions = (const float*)d_in[0];   // [1,512,256]
    const float* protein   = (const float*)d_in[1];   // [1,4096,1024]
    const float* Wc  = (const float*)d_in[2];
    const float* bc  = (const float*)d_in[3];
    const float* W1  = (const float*)d_in[4];
    const float* b1  = (const float*)d_in[5];
    const float* W2  = (const float*)d_in[6];
    const float* b2  = (const float*)d_in[7];
    const float* Wa  = (const float*)d_in[8];
    const float* ba  = (const float*)d_in[9];
    const float* Wpa = (const float*)d_in[10];
    const float* bpa = (const float*)d_in[11];
    const float* Wra = (const float*)d_in[12];
    const float* bra = (const float*)d_in[13];
    const float* Wf1 = (const float*)d_in[14];
    const float* bf1 = (const float*)d_in[15];
    const float* Wf2 = (const float*)d_in[16];
    const float* bf2 = (const float*)d_in[17];
    const float* Wf3 = (const float*)d_in[18];
    const float* bf3 = (const float*)d_in[19];
    float* out = (float*)d_out;

    float *p_, *k_, *pa_, *r_, *ra_, *S_, *T_, *rx_, *prot_;
    cudaGetSymbolAddress((void**)&p_, g_p);
    cudaGetSymbolAddress((void**)&k_, g_k);
    cudaGetSymbolAddress((void**)&pa_, g_pa);
    cudaGetSymbolAddress((void**)&r_, g_r);
    cudaGetSymbolAddress((void**)&ra_, g_ra);
    cudaGetSymbolAddress((void**)&S_, g_S);
    cudaGetSymbolAddress((void**)&T_, g_T);
    cudaGetSymbolAddress((void**)&rx_, g_rx);
    cudaGetSymbolAddress((void**)&prot_, g_prot);

    // zero accumulators (S and prot)
    zero_kernel<<<(Q * 64 + 255) / 256, 256>>>(S_, prot_, Q * 64);

    // p = relu(protein @ Wc.T + bc)   [4096,256], K=1024
    gemm_bias_act<1><<<dim3(L / 64, 256 / 64), 256>>>(protein, Wc, bc, p_, L, 256, 1024);
    // r = relu(reactions @ W2.T + b2) [512,64], K=256
    gemm_bias_act<1><<<dim3(Q / 64, 1), 256>>>(reactions, W2, b2, r_, Q, 64, 256);
    // k = relu(p @ W1.T + b1)         [4096,64], K=256
    gemm_bias_act<1><<<dim3(L / 64, 1), 256>>>(p_, W1, b1, k_, L, 64, 256);
    // ra = r @ Wra.T + bra            [512,64], K=64
    gemm_bias_act<0><<<dim3(Q / 64, 1), 256>>>(r_, Wra, bra, ra_, Q, 64, 64);
    // pa = k @ Wpa.T + bpa            [4096,64], K=64
    gemm_bias_act<0><<<dim3(L / 64, 1), 256>>>(k_, Wpa, bpa, pa_, L, 64, 64);

    // outer sums
    outer_S_kernel<<<dim3(Q / 16, L / 512), dim3(64, 8)>>>(ra_, pa_, S_);
    outer_T_kernel<<<dim3(L / 16, 1), dim3(64, 8)>>>(ra_, pa_, T_);

    // gates
    gate_r_kernel<<<dim3(Q / 8, 1), dim3(64, 8)>>>(S_, Wa, ba, r_, rx_);
    gate_p_kernel<<<dim3(L / 8, 1), dim3(64, 8)>>>(T_, Wa, ba, k_, prot_);

    // head
    head_kernel<<<dim3(Q / 8, 1), 256>>>(rx_, prot_, Wf1, bf1, Wf2, bf2, Wf3, bf3, out);
}

// round 15
// speedup vs baseline: 1.0167x; 1.0167x over previous
#include <cuda_runtime.h>
#include <cuda_bf16.h>
#include <stdint.h>
#include <math.h>

#define Q 512
#define L 4096

// ---------------- scratch ----------------
__device__ __nv_bfloat16 g_Ah[L * 1024];
__device__ __nv_bfloat16 g_Al[L * 1024];
__device__ __nv_bfloat16 g_Wh[256 * 1024];
__device__ __nv_bfloat16 g_Wl[256 * 1024];
__device__ float g_p[L * 256];
__device__ float g_k[L * 64];
__device__ float g_pa[L * 64];
__device__ float g_r[Q * 64];
__device__ float g_ra[Q * 64];
__device__ float g_S[Q * 64];
__device__ float g_T[L * 64];
__device__ float g_prot[64];

__global__ __launch_bounds__(256) void zero_kernel(float* s, float* prot, int n) {
    int i = blockIdx.x * blockDim.x + threadIdx.x;
    if (i < n) s[i] = 0.0f;
    if (i < 64) prot[i] = 0.0f;
}

// ---------------- bf16 hi/lo split conversion ----------------
__global__ __launch_bounds__(256) void convert_kernel(
        const float* __restrict__ prot, const float* __restrict__ Wc,
        __nv_bfloat16* __restrict__ Ah, __nv_bfloat16* __restrict__ Al,
        __nv_bfloat16* __restrict__ Wh, __nv_bfloat16* __restrict__ Wl) {
    const int NP = L * 1024;
    const int NW = 256 * 1024;
    int base = (blockIdx.x * 256 + threadIdx.x) * 4;
    if (base < NP) {
        float4 v = *(const float4*)&prot[base];
        float x[4] = {v.x, v.y, v.z, v.w};
#pragma unroll
        for (int i = 0; i < 4; i++) {
            __nv_bfloat16 h = __float2bfloat16_rn(x[i]);
            Ah[base + i] = h;
            Al[base + i] = __float2bfloat16_rn(x[i] - __bfloat162float(h));
        }
    } else {
        int j = base - NP;
        if (j < NW) {
            float4 v = *(const float4*)&Wc[j];
            float x[4] = {v.x, v.y, v.z, v.w};
#pragma unroll
            for (int i = 0; i < 4; i++) {
                __nv_bfloat16 h = __float2bfloat16_rn(x[i]);
                Wh[j + i] = h;
                Wl[j + i] = __float2bfloat16_rn(x[i] - __bfloat162float(h));
            }
        }
    }
}

// ---------------- mma.sync bf16 3-pass GEMM: p = relu(A @ Wc.T + bc) ----------------
// A [4096,1024], Wc [256,1024], p [4096,256]. Block tile 64x64, k-step 16.
// 8 warps: warp_m = wid>>1 (0..3, 16 rows each), warp_n = wid&1 (0..1, 32 cols each).
#define MMA_BF16(C0, C1, C2, C3, A0, A1, A2, A3, B0, B1)                      \
    asm volatile(                                                             \
        "mma.sync.aligned.m16n8k16.row.col.f32.bf16.bf16.f32 "                \
        "{%0,%1,%2,%3}, {%4,%5,%6,%7}, {%8,%9}, {%0,%1,%2,%3};"               \
        : "+f"(C0), "+f"(C1), "+f"(C2), "+f"(C3)                              \
        : "r"(A0), "r"(A1), "r"(A2), "r"(A3), "r"(B0), "r"(B1))

#define PSTR 24  // bf16 row stride in smem (16 data + 8 pad)

__global__ __launch_bounds__(256) void mma_p_kernel(
        const __nv_bfloat16* __restrict__ Ah, const __nv_bfloat16* __restrict__ Al,
        const __nv_bfloat16* __restrict__ Wh, const __nv_bfloat16* __restrict__ Wl,
        const float* __restrict__ bc, float* __restrict__ p) {
    __shared__ __nv_bfloat16 sAh[64 * PSTR], sAl[64 * PSTR];
    __shared__ __nv_bfloat16 sWh[64 * PSTR], sWl[64 * PSTR];
    const int tid = threadIdx.x;
    const int m0 = blockIdx.x * 64;
    const int n0 = blockIdx.y * 64;
    const int wid = tid >> 5, lane = tid & 31;
    const int wm = wid >> 1, wn = wid & 1;
    const int g = lane >> 2, t = lane & 3;
    const int sr = tid >> 2;          // 0..63 staging row
    const int sc = (tid & 3) * 4;     // 0,4,8,12 staging col

    float acc[4][4];
#pragma unroll
    for (int i = 0; i < 4; i++)
#pragma unroll
        for (int j = 0; j < 4; j++) acc[i][j] = 0.0f;

    for (int kk = 0; kk < 1024; kk += 16) {
        *(uint2*)&sAh[sr * PSTR + sc] = *(const uint2*)&Ah[(size_t)(m0 + sr) * 1024 + kk + sc];
        *(uint2*)&sAl[sr * PSTR + sc] = *(const uint2*)&Al[(size_t)(m0 + sr) * 1024 + kk + sc];
        *(uint2*)&sWh[sr * PSTR + sc] = *(const uint2*)&Wh[(size_t)(n0 + sr) * 1024 + kk + sc];
        *(uint2*)&sWl[sr * PSTR + sc] = *(const uint2*)&Wl[(size_t)(n0 + sr) * 1024 + kk + sc];
        __syncthreads();

        const int ar = wm * 16 + g;
        uint32_t a_h[4], a_l[4];
        a_h[0] = *(const uint32_t*)&sAh[ar * PSTR + 2 * t];
        a_h[1] = *(const uint32_t*)&sAh[(ar + 8) * PSTR + 2 * t];
        a_h[2] = *(const uint32_t*)&sAh[ar * PSTR + 2 * t + 8];
        a_h[3] = *(const uint32_t*)&sAh[(ar + 8) * PSTR + 2 * t + 8];
        a_l[0] = *(const uint32_t*)&sAl[ar * PSTR + 2 * t];
        a_l[1] = *(const uint32_t*)&sAl[(ar + 8) * PSTR + 2 * t];
        a_l[2] = *(const uint32_t*)&sAl[ar * PSTR + 2 * t + 8];
        a_l[3] = *(const uint32_t*)&sAl[(ar + 8) * PSTR + 2 * t + 8];

#pragma unroll
        for (int np = 0; np < 4; np++) {
            const int bn = wn * 32 + np * 8 + g;
            uint32_t bh0 = *(const uint32_t*)&sWh[bn * PSTR + 2 * t];
            uint32_t bh1 = *(const uint32_t*)&sWh[bn * PSTR + 2 * t + 8];
            uint32_t bl0 = *(const uint32_t*)&sWl[bn * PSTR + 2 * t];
            uint32_t bl1 = *(const uint32_t*)&sWl[bn * PSTR + 2 * t + 8];
            MMA_BF16(acc[np][0], acc[np][1], acc[np][2], acc[np][3],
                     a_h[0], a_h[1], a_h[2], a_h[3], bh0, bh1);
            MMA_BF16(acc[np][0], acc[np][1], acc[np][2], acc[np][3],
                     a_h[0], a_h[1], a_h[2], a_h[3], bl0, bl1);
            MMA_BF16(acc[np][0], acc[np][1], acc[np][2], acc[np][3],
                     a_l[0], a_l[1], a_l[2], a_l[3], bh0, bh1);
        }
        __syncthreads();
    }

    const int prow0 = m0 + wm * 16 + g;
#pragma unroll
    for (int np = 0; np < 4; np++) {
        const int pc = n0 + wn * 32 + np * 8 + 2 * t;
        const float b0v = bc[pc], b1v = bc[pc + 1];
        p[(size_t)prow0 * 256 + pc]             = fmaxf(acc[np][0] + b0v, 0.0f);
        p[(size_t)prow0 * 256 + pc + 1]         = fmaxf(acc[np][1] + b1v, 0.0f);
        p[(size_t)(prow0 + 8) * 256 + pc]       = fmaxf(acc[np][2] + b0v, 0.0f);
        p[(size_t)(prow0 + 8) * 256 + pc + 1]   = fmaxf(acc[np][3] + b1v, 0.0f);
    }
}

// ---------------- fused 2-stage chain: outK = relu(A@W1.T + b1); outA = outK@W2.T + b2
// A [M,256], W1 [64,256], W2 [64,64]. BM=32, 256 threads, grid M/32.
__global__ __launch_bounds__(256) void chain2_kernel(
        const float* __restrict__ A,
        const float* __restrict__ W1_, const float* __restrict__ b1_,
        const float* __restrict__ W2_, const float* __restrict__ b2_,
        float* __restrict__ outK, float* __restrict__ outA) {
    __shared__ float sA[32][36];
    __shared__ float sWt[32][72];   // W1 chunk transposed [k][n]
    __shared__ float sK[32][72];
    __shared__ float sW2t[64][72];  // W2 transposed [k][n]
    const int tid = threadIdx.x;
    const int m0 = blockIdx.x * 32;
    const int ty = tid >> 3;   // 0..31 (m)
    const int tx = tid & 7;    // n group of 8

    float acc[8];
#pragma unroll
    for (int j = 0; j < 8; j++) acc[j] = 0.0f;

    for (int kk = 0; kk < 256; kk += 32) {
        *(float4*)&sA[ty][tx * 4] = *(const float4*)&A[(size_t)(m0 + ty) * 256 + kk + tx * 4];
        {
            const int n = tid & 63;
            const int c0 = (tid >> 6) * 8;
            const float4 v0 = *(const float4*)&W1_[(size_t)n * 256 + kk + c0];
            const float4 v1 = *(const float4*)&W1_[(size_t)n * 256 + kk + c0 + 4];
            sWt[c0 + 0][n] = v0.x; sWt[c0 + 1][n] = v0.y;
            sWt[c0 + 2][n] = v0.z; sWt[c0 + 3][n] = v0.w;
            sWt[c0 + 4][n] = v1.x; sWt[c0 + 5][n] = v1.y;
            sWt[c0 + 6][n] = v1.z; sWt[c0 + 7][n] = v1.w;
        }
        __syncthreads();
#pragma unroll
        for (int k = 0; k < 32; k++) {
            const float a = sA[ty][k];
            const float4 w0 = *(const float4*)&sWt[k][tx * 8];
            const float4 w1 = *(const float4*)&sWt[k][tx * 8 + 4];
            acc[0] = fmaf(a, w0.x, acc[0]); acc[1] = fmaf(a, w0.y, acc[1]);
            acc[2] = fmaf(a, w0.z, acc[2]); acc[3] = fmaf(a, w0.w, acc[3]);
            acc[4] = fmaf(a, w1.x, acc[4]); acc[5] = fmaf(a, w1.y, acc[5]);
            acc[6] = fmaf(a, w1.z, acc[6]); acc[7] = fmaf(a, w1.w, acc[7]);
        }
        __syncthreads();
    }
#pragma unroll
    for (int j = 0; j < 8; j++) {
        const float v = fmaxf(acc[j] + b1_[tx * 8 + j], 0.0f);
        sK[ty][tx * 8 + j] = v;
        outK[(size_t)(m0 + ty) * 64 + tx * 8 + j] = v;
    }
    {
        const int n = tid & 63;
        const int c0 = (tid >> 6) * 16;
#pragma unroll
        for (int cc = 0; cc < 16; cc += 4) {
            const float4 v = *(const float4*)&W2_[(size_t)n * 64 + c0 + cc];
            sW2t[c0 + cc + 0][n] = v.x; sW2t[c0 + cc + 1][n] = v.y;
            sW2t[c0 + cc + 2][n] = v.z; sW2t[c0 + cc + 3][n] = v.w;
        }
    }
    __syncthreads();
    float acc2[8];
#pragma unroll
    for (int j = 0; j < 8; j++) acc2[j] = 0.0f;
#pragma unroll
    for (int k = 0; k < 64; k++) {
        const float a = sK[ty][k];
        const float4 w0 = *(const float4*)&sW2t[k][tx * 8];
        const float4 w1 = *(const float4*)&sW2t[k][tx * 8 + 4];
        acc2[0] = fmaf(a, w0.x, acc2[0]); acc2[1] = fmaf(a, w0.y, acc2[1]);
        acc2[2] = fmaf(a, w0.z, acc2[2]); acc2[3] = fmaf(a, w0.w, acc2[3]);
        acc2[4] = fmaf(a, w1.x, acc2[4]); acc2[5] = fmaf(a, w1.y, acc2[5]);
        acc2[6] = fmaf(a, w1.z, acc2[6]); acc2[7] = fmaf(a, w1.w, acc2[7]);
    }
#pragma unroll
    for (int j = 0; j < 8; j++)
        outA[(size_t)(m0 + ty) * 64 + tx * 8 + j] = acc2[j] + b2_[tx * 8 + j];
}

// ---------------- outer-sum passes ----------------
__global__ __launch_bounds__(512) void outer_S_kernel(
        const float* __restrict__ ra, const float* __restrict__ pa,
        float* __restrict__ S) {
    __shared__ float spa[64][64];
    const int tx = threadIdx.x, ty = threadIdx.y;
    const int tid = ty * 64 + tx;
    const int q0 = blockIdx.x * 16 + ty * 2;
    const int l0 = blockIdx.y * 512;
    const float r0 = ra[q0 * 64 + tx];
    const float r1 = ra[(q0 + 1) * 64 + tx];
    float a0 = 0.0f, a1 = 0.0f;
    for (int lc = 0; lc < 512; lc += 64) {
        __syncthreads();
#pragma unroll
        for (int i = 0; i < 8; i++) {
            int e = tid + i * 512;
            spa[e >> 6][e & 63] = pa[(l0 + lc + (e >> 6)) * 64 + (e & 63)];
        }
        __syncthreads();
#pragma unroll
        for (int i = 0; i < 64; i++) {
            float v = spa[i][tx];
            a0 += fmaxf(r0 + v, 0.0f);
            a1 += fmaxf(r1 + v, 0.0f);
        }
    }
    atomicAdd(&S[q0 * 64 + tx], a0);
    atomicAdd(&S[(q0 + 1) * 64 + tx], a1);
}

__global__ __launch_bounds__(512) void outer_T_kernel(
        const float* __restrict__ ra, const float* __restrict__ pa,
        float* __restrict__ T) {
    __shared__ float sra[64][64];
    const int tx = threadIdx.x, ty = threadIdx.y;
    const int tid = ty * 64 + tx;
    const int l0 = blockIdx.x * 16 + ty * 2;
    const float p0 = pa[l0 * 64 + tx];
    const float p1 = pa[(l0 + 1) * 64 + tx];
    float a0 = 0.0f, a1 = 0.0f;
    for (int qc = 0; qc < Q; qc += 64) {
        __syncthreads();
#pragma unroll
        for (int i = 0; i < 8; i++) {
            int e = tid + i * 512;
            sra[e >> 6][e & 63] = ra[(qc + (e >> 6)) * 64 + (e & 63)];
        }
        __syncthreads();
#pragma unroll
        for (int i = 0; i < 64; i++) {
            float v = sra[i][tx];
            a0 += fmaxf(p0 + v, 0.0f);
            a1 += fmaxf(p1 + v, 0.0f);
        }
    }
    T[l0 * 64 + tx] = a0;
    T[(l0 + 1) * 64 + tx] = a1;
}

// ---------------- gate_p (prot via atomicMax over nonneg) ----------------
__global__ __launch_bounds__(512) void gate_p_kernel(
        const float* __restrict__ T, const float* __restrict__ Wa,
        const float* __restrict__ ba, const float* __restrict__ k,
        float* __restrict__ prot) {
    __shared__ float sWa[64][65];
    __shared__ float sT[8][64];
    __shared__ float skp[8][64];
    const int tx = threadIdx.x, ty = threadIdx.y;
    const int tid = ty * 64 + tx;
    const int l0 = blockIdx.x * 8;
#pragma unroll
    for (int i = 0; i < 8; i++) {
        int e = tid + i * 512;
        sWa[e >> 6][e & 63] = Wa[e];
    }
    sT[tid >> 6][tid & 63] = T[(l0 + (tid >> 6)) * 64 + (tid & 63)];
    __syncthreads();
    float acc = 0.0f;
#pragma unroll
    for (int j = 0; j < 64; j++) acc += sT[ty][j] * sWa[tx][j];
    float x = ba[tx] + acc * (1.0f / (float)Q);
    float g = 1.0f / (1.0f + expf(-x));
    float kv = k[(l0 + ty) * 64 + tx];
    skp[ty][tx] = kv * (1.0f + g);
    __syncthreads();
    if (ty == 0) {
        float m = skp[0][tx];
#pragma unroll
        for (int i = 1; i < 8; i++) m = fmaxf(m, skp[i][tx]);
        atomicMax((int*)&prot[tx], __float_as_int(m));
    }
}

// ---------------- fused gate_r + MLP head: 8 q per block, 256 threads ----------------
__global__ __launch_bounds__(256) void gate_r_head_kernel(
        const float* __restrict__ S, const float* __restrict__ Wa,
        const float* __restrict__ ba, const float* __restrict__ r,
        const float* __restrict__ prot,
        const float* __restrict__ Wf1, const float* __restrict__ bf1,
        const float* __restrict__ Wf2, const float* __restrict__ bf2,
        const float* __restrict__ Wf3, const float* __restrict__ bf3,
        float* __restrict__ out) {
    __shared__ float sWa[64][65];
    __shared__ float sS[8][64];
    __shared__ float sctx[8][128];
    __shared__ float sh1[8][256];
    __shared__ float sh2[8][128];
    const int tid = threadIdx.x;
    const int q0 = blockIdx.x * 8;
#pragma unroll
    for (int i = 0; i < 16; i++) {
        int e = tid + i * 256;
        sWa[e >> 6][e & 63] = Wa[e];
    }
#pragma unroll
    for (int i = 0; i < 2; i++) {
        int e = tid + i * 256;
        sS[e >> 6][e & 63] = S[(q0 + (e >> 6)) * 64 + (e & 63)];
    }
    __syncthreads();
#pragma unroll
    for (int i = 0; i < 2; i++) {
        int o = tid + i * 256;
        int qq = o >> 6, c = o & 63;
        float acc = 0.0f;
#pragma unroll
        for (int j = 0; j < 64; j++) acc += sS[qq][j] * sWa[c][j];
        float x = ba[c] + acc * (1.0f / (float)L);
        float g = 1.0f / (1.0f + expf(-x));
        sctx[qq][c] = r[(q0 + qq) * 64 + c] * (1.0f + g);
        sctx[qq][64 + c] = prot[c];
    }
    __syncthreads();
    {
        float acc[8];
        float b = bf1[tid];
#pragma unroll
        for (int qq = 0; qq < 8; qq++) acc[qq] = b;
        for (int kk = 0; kk < 128; kk++) {
            float w = Wf1[tid * 128 + kk];
#pragma unroll
            for (int qq = 0; qq < 8; qq++) acc[qq] = fmaf(w, sctx[qq][kk], acc[qq]);
        }
#pragma unroll
        for (int qq = 0; qq < 8; qq++) {
            float v = acc[qq];
            sh1[qq][tid] = (v > 0.0f) ? v : 0.01f * v;
        }
    }
    __syncthreads();
    if (tid < 128) {
        float acc[8];
        float b = bf2[tid];
#pragma unroll
        for (int qq = 0; qq < 8; qq++) acc[qq] = b;
        for (int kk = 0; kk < 256; kk++) {
            float w = Wf2[tid * 256 + kk];
#pragma unroll
            for (int qq = 0; qq < 8; qq++) acc[qq] = fmaf(w, sh1[qq][kk], acc[qq]);
        }
#pragma unroll
        for (int qq = 0; qq < 8; qq++) {
            float v = acc[qq];
            sh2[qq][tid] = (v > 0.0f) ? v : 0.01f * v;
        }
    }
    __syncthreads();
    const int wq = tid >> 5, lane = tid & 31;
    float s = 0.0f;
#pragma unroll
    for (int kk = lane; kk < 128; kk += 32) s = fmaf(Wf3[kk], sh2[wq][kk], s);
#pragma unroll
    for (int off = 16; off; off >>= 1) s += __shfl_xor_sync(0xffffffffu, s, off);
    if (lane == 0) out[q0 + wq] = s + bf3[0];
}

// ---------------- launch ----------------
extern "C" void kernel_launch(void* const* d_in, const int* in_sizes, int n_in,
                              void* d_out, int out_size) {
    const float* reactions = (const float*)d_in[0];
    const float* protein   = (const float*)d_in[1];
    const float* Wc  = (const float*)d_in[2];
    const float* bc  = (const float*)d_in[3];
    const float* W1  = (const float*)d_in[4];
    const float* b1  = (const float*)d_in[5];
    const float* W2  = (const float*)d_in[6];
    const float* b2  = (const float*)d_in[7];
    const float* Wa  = (const float*)d_in[8];
    const float* ba  = (const float*)d_in[9];
    const float* Wpa = (const float*)d_in[10];
    const float* bpa = (const float*)d_in[11];
    const float* Wra = (const float*)d_in[12];
    const float* bra = (const float*)d_in[13];
    const float* Wf1 = (const float*)d_in[14];
    const float* bf1 = (const float*)d_in[15];
    const float* Wf2 = (const float*)d_in[16];
    const float* bf2 = (const float*)d_in[17];
    const float* Wf3 = (const float*)d_in[18];
    const float* bf3 = (const float*)d_in[19];
    float* out = (float*)d_out;

    __nv_bfloat16 *Ah_, *Al_, *Wh_, *Wl_;
    float *p_, *k_, *pa_, *r_, *ra_, *S_, *T_, *prot_;
    cudaGetSymbolAddress((void**)&Ah_, g_Ah);
    cudaGetSymbolAddress((void**)&Al_, g_Al);
    cudaGetSymbolAddress((void**)&Wh_, g_Wh);
    cudaGetSymbolAddress((void**)&Wl_, g_Wl);
    cudaGetSymbolAddress((void**)&p_, g_p);
    cudaGetSymbolAddress((void**)&k_, g_k);
    cudaGetSymbolAddress((void**)&pa_, g_pa);
    cudaGetSymbolAddress((void**)&r_, g_r);
    cudaGetSymbolAddress((void**)&ra_, g_ra);
    cudaGetSymbolAddress((void**)&S_, g_S);
    cudaGetSymbolAddress((void**)&T_, g_T);
    cudaGetSymbolAddress((void**)&prot_, g_prot);

    zero_kernel<<<(Q * 64 + 255) / 256, 256>>>(S_, prot_, Q * 64);
    {
        int total4 = (L * 1024 + 256 * 1024) / 4;
        convert_kernel<<<(total4 + 255) / 256, 256>>>(protein, Wc, Ah_, Al_, Wh_, Wl_);
    }
    mma_p_kernel<<<dim3(L / 64, 256 / 64), 256>>>(Ah_, Al_, Wh_, Wl_, bc, p_);
    chain2_kernel<<<Q / 32, 256>>>(reactions, W2, b2, Wra, bra, r_, ra_);
    chain2_kernel<<<L / 32, 256>>>(p_, W1, b1, Wpa, bpa, k_, pa_);
    outer_S_kernel<<<dim3(Q / 16, L / 512), dim3(64, 8)>>>(ra_, pa_, S_);
    outer_T_kernel<<<dim3(L / 16, 1), dim3(64, 8)>>>(ra_, pa_, T_);
    gate_p_kernel<<<dim3(L / 8, 1), dim3(64, 8)>>>(T_, Wa, ba, k_, prot_);
    gate_r_head_kernel<<<dim3(Q / 8, 1), 256>>>(S_, Wa, ba, r_, prot_,
                                                Wf1, bf1, Wf2, bf2, Wf3, bf3, out);
}